// round 2
// baseline (speedup 1.0000x reference)
#include <cuda_runtime.h>
#include <math.h>
#include <stdint.h>

#define L_SEQ   600
#define BATCH   64
#define DSPEC   552
#define DPRE    256
#define DH      1024
#define G4      4096
#define MROWS   (L_SEQ*BATCH)   // 38400
#define NBLK    128

typedef unsigned long long ull;

// ---------------- static device scratch ----------------
static __device__ float g_pre1 [(size_t)MROWS*DPRE];
static __device__ float g_pre2 [(size_t)MROWS*DPRE];
static __device__ float g_g0xT [(size_t)L_SEQ*G4*BATCH];     // [t][gate][b]
static __device__ float g_ht0  [2][DH*BATCH];                // transposed h0 [k][b]
static __device__ float g_ht1  [2][DH*BATCH];
static __device__ float g_c0t  [DH*BATCH];
static __device__ float g_c1t  [DH*BATCH];
static __device__ float g_outs [(size_t)MROWS*DH];           // [t][b][1024]
static __device__ float g_spred[(size_t)BATCH*DSPEC*L_SEQ];  // [B][552][600]
static __device__ float g_cbA  [(size_t)BATCH*DSPEC*L_SEQ];
static __device__ float g_cbB  [(size_t)BATCH*DSPEC*L_SEQ];
static __device__ unsigned int g_barctr;

__device__ __forceinline__ float sigmoidf_(float x) { return 1.0f / (1.0f + expf(-x)); }

__device__ __forceinline__ ull splat2(float w) {
    ull r; asm("mov.b64 %0, {%1, %1};" : "=l"(r) : "f"(w)); return r;
}
__device__ __forceinline__ void fma2(ull& d, ull a, ull b) {
    asm("fma.rn.f32x2 %0, %1, %2, %0;" : "+l"(d) : "l"(a), "l"(b));
}

// ---------------- init ----------------
__global__ void init_kernel() {
    int i = blockIdx.x * blockDim.x + threadIdx.x;
    if (i == 0) g_barctr = 0u;
    int stride = gridDim.x * blockDim.x;
    for (int j = i; j < DH*BATCH; j += stride) {
        g_ht0[0][j] = 0.f; g_ht1[0][j] = 0.f; g_c0t[j] = 0.f; g_c1t[j] = 0.f;
    }
}

// ---------------- generic GEMM: C[M,N] = A[M,K] @ W[N,K]^T + b1 + b2 ----------------
// a_shift: row m -> (m<64 ? zeros : A[m-64])
// c_mode : 0 -> C[m*N+n] ; 1 -> C[b*N*600 + n*600 + t] ; 2 -> C[(t*N+n)*64 + b]
__global__ void gemm_kernel(const float* __restrict__ A, const float* __restrict__ W,
                            const float* __restrict__ b1, const float* __restrict__ b2,
                            float* __restrict__ C, int M, int N, int K, int wstride,
                            int a_shift, int act, int c_mode)
{
    __shared__ float sA[16][64];
    __shared__ float sW[16][64];
    int tid = threadIdx.x;                  // 256 threads
    int m0 = blockIdx.y * 64, n0 = blockIdx.x * 64;
    int tm = tid & 15, tn = tid >> 4;
    float acc[4][4];
#pragma unroll
    for (int i = 0; i < 4; i++)
#pragma unroll
        for (int j = 0; j < 4; j++) acc[i][j] = 0.f;

    for (int k0 = 0; k0 < K; k0 += 16) {
        {
            int m = tid >> 2, kq = tid & 3;
            int gm = m0 + m, gk = k0 + kq * 4;
            float4 v = make_float4(0.f, 0.f, 0.f, 0.f);
            int row = gm; bool okrow = true;
            if (a_shift) { row = gm - 64; okrow = (row >= 0); }
            if (okrow) {
                const float* p = A + (size_t)row * K + gk;
                if (gk + 4 <= K) v = *(const float4*)p;
                else {
                    if (gk + 0 < K) v.x = p[0];
                    if (gk + 1 < K) v.y = p[1];
                    if (gk + 2 < K) v.z = p[2];
                    if (gk + 3 < K) v.w = p[3];
                }
            }
            sA[kq*4+0][m] = v.x; sA[kq*4+1][m] = v.y; sA[kq*4+2][m] = v.z; sA[kq*4+3][m] = v.w;
        }
        {
            int n = tid >> 2, kq = tid & 3;
            int gn = n0 + n, gk = k0 + kq * 4;
            float4 v = make_float4(0.f, 0.f, 0.f, 0.f);
            if (gn < N) {
                const float* p = W + (size_t)gn * wstride + gk;
                if (gk + 4 <= K) v = *(const float4*)p;
                else {
                    if (gk + 0 < K) v.x = p[0];
                    if (gk + 1 < K) v.y = p[1];
                    if (gk + 2 < K) v.z = p[2];
                    if (gk + 3 < K) v.w = p[3];
                }
            }
            sW[kq*4+0][n] = v.x; sW[kq*4+1][n] = v.y; sW[kq*4+2][n] = v.z; sW[kq*4+3][n] = v.w;
        }
        __syncthreads();
#pragma unroll
        for (int k = 0; k < 16; k++) {
            float4 av = *(float4*)&sA[k][tm*4];
            float4 wv = *(float4*)&sW[k][tn*4];
            float a[4] = {av.x, av.y, av.z, av.w};
            float w[4] = {wv.x, wv.y, wv.z, wv.w};
#pragma unroll
            for (int i = 0; i < 4; i++)
#pragma unroll
                for (int j = 0; j < 4; j++) acc[i][j] += a[i] * w[j];
        }
        __syncthreads();
    }
#pragma unroll
    for (int i = 0; i < 4; i++) {
        int gm = m0 + tm*4 + i;
#pragma unroll
        for (int j = 0; j < 4; j++) {
            int gn = n0 + tn*4 + j;
            if (gn < N) {
                float v = acc[i][j];
                if (b1) v += b1[gn];
                if (b2) v += b2[gn];
                if (act) v = fmaxf(v, 0.f);
                if (c_mode == 0) C[(size_t)gm * N + gn] = v;
                else if (c_mode == 1) {
                    int t = gm >> 6, b = gm & 63;
                    C[(size_t)b * N * 600 + (size_t)gn * 600 + t] = v;
                } else {
                    int t = gm >> 6, b = gm & 63;
                    C[((size_t)t * N + gn) * 64 + b] = v;
                }
            }
        }
    }
}

// ---------------- persistent LSTM recurrence ----------------
// 128 blocks x 256 threads. Block owns jj in [jj0, jj0+8) i.e. 32 gate rows
// (8 jj x 4 gates). Per phase: tile 32 rows x 64 batch (32 f32-pairs), thread
// micro-tile = 4 rows x 4 pairs, 4-way K-slice (s = tid&3).

__device__ __forceinline__ void grid_bar(unsigned int target) {
    __threadfence();
    __syncthreads();
    if (threadIdx.x == 0) {
        atomicAdd(&g_barctr, 1u);
        unsigned int cur;
        do {
            asm volatile("ld.acquire.gpu.u32 %0, [%1];" : "=r"(cur) : "l"(&g_barctr) : "memory");
        } while (cur < target);
    }
    __syncthreads();
}

__device__ __forceinline__ void fill_tile(const float* __restrict__ hsrc,  // rows k0.., [k][64]
                                          const float* __restrict__ wsrc,  // W + k0 (col offset)
                                          int jj0, int tid,
                                          float2 (*sh2)[34], float (*sw)[36])
{
#pragma unroll
    for (int q = 0; q < 4; q++) {
        int idx = q * 256 + tid;
        int k = idx >> 4, f = idx & 15;
        float4 v = *(const float4*)(hsrc + (size_t)k * 64 + f * 4);
        *(float4*)&sh2[k][f * 2] = v;
    }
#pragma unroll
    for (int q = 0; q < 2; q++) {
        int idx = q * 256 + tid;
        int wrow = idx >> 4, kq = idx & 15;
        int gate = (wrow >> 3) * 1024 + jj0 + (wrow & 7);
        float4 v = *(const float4*)(wsrc + (size_t)gate * DH + kq * 4);
        sw[kq*4+0][wrow] = v.x; sw[kq*4+1][wrow] = v.y;
        sw[kq*4+2][wrow] = v.z; sw[kq*4+3][wrow] = v.w;
    }
}

__device__ __forceinline__ void mma_tile(ull acc[4][4], int s, int pairg, int rowg,
                                         float2 (*sh2)[34], float (*sw)[36])
{
#pragma unroll
    for (int kk = 0; kk < 16; kk++) {
        int k = kk * 4 + s;
        float4 wv = *(const float4*)&sw[k][rowg * 4];
        ull w0 = splat2(wv.x), w1 = splat2(wv.y), w2 = splat2(wv.z), w3 = splat2(wv.w);
        ulonglong2 ha = *(const ulonglong2*)&sh2[k][pairg * 4];
        ulonglong2 hb = *(const ulonglong2*)&sh2[k][pairg * 4 + 2];
        fma2(acc[0][0], w0, ha.x); fma2(acc[0][1], w0, ha.y);
        fma2(acc[0][2], w0, hb.x); fma2(acc[0][3], w0, hb.y);
        fma2(acc[1][0], w1, ha.x); fma2(acc[1][1], w1, ha.y);
        fma2(acc[1][2], w1, hb.x); fma2(acc[1][3], w1, hb.y);
        fma2(acc[2][0], w2, ha.x); fma2(acc[2][1], w2, ha.y);
        fma2(acc[2][2], w2, hb.x); fma2(acc[2][3], w2, hb.y);
        fma2(acc[3][0], w3, ha.x); fma2(acc[3][1], w3, ha.y);
        fma2(acc[3][2], w3, hb.x); fma2(acc[3][3], w3, hb.y);
    }
}

__device__ __forceinline__ void reduce_acc(ull acc[4][4], int s, int pairg, int rowg,
                                           float (*gsum)[66])
{
#pragma unroll
    for (int turn = 0; turn < 4; turn++) {
        if (s == turn) {
#pragma unroll
            for (int i = 0; i < 4; i++)
#pragma unroll
                for (int j = 0; j < 4; j++) {
                    float lo = __uint_as_float((unsigned)(acc[i][j] & 0xFFFFFFFFull));
                    float hi = __uint_as_float((unsigned)(acc[i][j] >> 32));
                    int row = rowg * 4 + i;
                    int b = (pairg * 4 + j) * 2;
                    if (turn == 0) { gsum[row][b] = lo; gsum[row][b+1] = hi; }
                    else           { gsum[row][b] += lo; gsum[row][b+1] += hi; }
                }
        }
        __syncthreads();
    }
}

__global__ __launch_bounds__(256, 1)
void lstm_persistent(const float* __restrict__ Whh0,
                     const float* __restrict__ Wih1,
                     const float* __restrict__ Whh1,
                     const float* __restrict__ bih1,
                     const float* __restrict__ bhh1)
{
    __shared__ float2 sh2[64][34];
    __shared__ float  sw [64][36];
    __shared__ float  gsum[32][66];

    int tid = threadIdx.x;
    int jj0 = blockIdx.x * 8;
    int s = tid & 3, pairg = (tid >> 2) & 7, rowg = tid >> 5;
    unsigned int ep = 0;
    ull acc[4][4];

    for (int t = 0; t < L_SEQ; t++) {
        // ================= phase A : layer 0 =================
        const float* hin  = g_ht0[t & 1];
        float*       h0w  = g_ht0[(t + 1) & 1];
#pragma unroll
        for (int i = 0; i < 4; i++)
#pragma unroll
            for (int j = 0; j < 4; j++) acc[i][j] = 0ull;
        for (int c = 0; c < 16; c++) {
            int k0 = c * 64;
            __syncthreads();
            fill_tile(hin + (size_t)k0 * 64, Whh0 + k0, jj0, tid, sh2, sw);
            __syncthreads();
            mma_tile(acc, s, pairg, rowg, sh2, sw);
        }
        reduce_acc(acc, s, pairg, rowg, gsum);
        // cell
        {
            const float* gx = g_g0xT + (size_t)t * G4 * 64;
#pragma unroll
            for (int e = 0; e < 2; e++) {
                int cidx = e * 256 + tid;
                int b = cidx & 63, jr = cidx >> 6;
                int jj = jj0 + jr;
                float gi = gsum[jr     ][b] + gx[((size_t)(       jj)) * 64 + b];
                float gf = gsum[8  + jr][b] + gx[((size_t)(1024 + jj)) * 64 + b];
                float gg = gsum[16 + jr][b] + gx[((size_t)(2048 + jj)) * 64 + b];
                float go = gsum[24 + jr][b] + gx[((size_t)(3072 + jj)) * 64 + b];
                float cc = g_c0t[jj * 64 + b];
                float cn = sigmoidf_(gf) * cc + sigmoidf_(gi) * tanhf(gg);
                float hn = sigmoidf_(go) * tanhf(cn);
                g_c0t[jj * 64 + b] = cn;
                h0w[jj * 64 + b] = hn;
            }
        }
        grid_bar(++ep * NBLK);

        // ================= phase B : layer 1 =================
        const float* h0n  = g_ht0[(t + 1) & 1];
        const float* h1in = g_ht1[t & 1];
        float*       h1w  = g_ht1[(t + 1) & 1];
#pragma unroll
        for (int i = 0; i < 4; i++)
#pragma unroll
            for (int j = 0; j < 4; j++) acc[i][j] = 0ull;
        for (int c = 0; c < 32; c++) {
            const float* hs; const float* ws;
            if (c < 16) { int k0 = c * 64;        hs = h0n  + (size_t)k0 * 64; ws = Wih1 + k0; }
            else        { int k0 = (c - 16) * 64; hs = h1in + (size_t)k0 * 64; ws = Whh1 + k0; }
            __syncthreads();
            fill_tile(hs, ws, jj0, tid, sh2, sw);
            __syncthreads();
            mma_tile(acc, s, pairg, rowg, sh2, sw);
        }
        reduce_acc(acc, s, pairg, rowg, gsum);
        // cell
        {
#pragma unroll
            for (int e = 0; e < 2; e++) {
                int cidx = e * 256 + tid;
                int b = cidx & 63, jr = cidx >> 6;
                int jj = jj0 + jr;
                float gi = gsum[jr     ][b] + bih1[       jj] + bhh1[       jj];
                float gf = gsum[8  + jr][b] + bih1[1024 + jj] + bhh1[1024 + jj];
                float gg = gsum[16 + jr][b] + bih1[2048 + jj] + bhh1[2048 + jj];
                float go = gsum[24 + jr][b] + bih1[3072 + jj] + bhh1[3072 + jj];
                float cc = g_c1t[jj * 64 + b];
                float cn = sigmoidf_(gf) * cc + sigmoidf_(gi) * tanhf(gg);
                float hn = sigmoidf_(go) * tanhf(cn);
                g_c1t[jj * 64 + b] = cn;
                h1w[jj * 64 + b] = hn;
                g_outs[((size_t)t * 64 + b) * DH + jj] = hn;
            }
        }
        grid_bar(++ep * NBLK);
    }
}

// ---------------- conv1d (K=5, same padding) ----------------
__global__ void conv_kernel(const float* __restrict__ x, const float* __restrict__ w,
                            const float* __restrict__ bias, float* __restrict__ out,
                            int Cin, int Cout, int mode, const float* __restrict__ spred)
{
    __shared__ float sx[8][260];
    __shared__ float swt[16][8][5];
    int b   = blockIdx.z;
    int co0 = blockIdx.y * 16;
    int lt0 = blockIdx.x * 256;
    int tid = threadIdx.x;            // 128 threads
    int tc = tid >> 5;
    int tl = tid & 31;
    float acc[4][8];
#pragma unroll
    for (int ci = 0; ci < 4; ci++)
#pragma unroll
        for (int j = 0; j < 8; j++) acc[ci][j] = 0.f;

    for (int ci0 = 0; ci0 < Cin; ci0 += 8) {
        __syncthreads();
        for (int idx = tid; idx < 8 * 260; idx += 128) {
            int ci = idx / 260, lc = idx % 260;
            int gl = lt0 - 2 + lc;
            sx[ci][lc] = (gl >= 0 && gl < 600) ? x[((size_t)b * Cin + ci0 + ci) * 600 + gl] : 0.f;
        }
        for (int idx = tid; idx < 16 * 8 * 5; idx += 128) {
            int co = idx / 40, r = idx % 40;
            int ci = r / 5, k = r % 5;
            float v = 0.f;
            if (co0 + co < Cout) v = w[(((size_t)(co0 + co)) * Cin + ci0 + ci) * 5 + k];
            swt[co][ci][k] = v;
        }
        __syncthreads();
#pragma unroll
        for (int ci = 0; ci < 8; ci++) {
            float xr[12];
#pragma unroll
            for (int i = 0; i < 12; i++) xr[i] = sx[ci][tl * 8 + i];
#pragma unroll
            for (int k = 0; k < 5; k++)
#pragma unroll
                for (int cg = 0; cg < 4; cg++) {
                    float wv = swt[tc * 4 + cg][ci][k];
#pragma unroll
                    for (int j = 0; j < 8; j++) acc[cg][j] += wv * xr[j + k];
                }
        }
    }
#pragma unroll
    for (int cg = 0; cg < 4; cg++) {
        int co = co0 + tc * 4 + cg;
        if (co >= Cout) continue;
#pragma unroll
        for (int j = 0; j < 8; j++) {
            int l = lt0 + tl * 8 + j;
            if (l >= 600) continue;
            float v = acc[cg][j] + bias[co];
            if (mode == 0)
                out[((size_t)b * Cout + co) * 600 + l] = tanhf(v);
            else {
                v += spred[((size_t)b * Cout + co) * 600 + l];
                out[((size_t)l * 64 + b) * 552 + co] = v;
            }
        }
    }
}

// ---------------- launcher ----------------
extern "C" void kernel_launch(void* const* d_in, const int* in_sizes, int n_in,
                              void* d_out, int out_size)
{
    const float* S_pad  = (const float*)d_in[0];
    const float* pre_W1 = (const float*)d_in[1];
    const float* pre_b1 = (const float*)d_in[2];
    const float* pre_W2 = (const float*)d_in[3];
    const float* pre_b2 = (const float*)d_in[4];
    const float* Wih0   = (const float*)d_in[5];
    const float* Whh0   = (const float*)d_in[6];
    const float* bih0   = (const float*)d_in[7];
    const float* bhh0   = (const float*)d_in[8];
    const float* Wih1   = (const float*)d_in[9];
    const float* Whh1   = (const float*)d_in[10];
    const float* bih1   = (const float*)d_in[11];
    const float* bhh1   = (const float*)d_in[12];
    const float* lin_W  = (const float*)d_in[13];
    const float* lin_b  = (const float*)d_in[14];
    const float* cw1 = (const float*)d_in[15];
    const float* cb1 = (const float*)d_in[16];
    const float* cw2 = (const float*)d_in[17];
    const float* cb2 = (const float*)d_in[18];
    const float* cw3 = (const float*)d_in[19];
    const float* cb3 = (const float*)d_in[20];
    const float* cw4 = (const float*)d_in[21];
    const float* cb4 = (const float*)d_in[22];
    const float* cw5 = (const float*)d_in[23];
    const float* cb5 = (const float*)d_in[24];

    float *pre1, *pre2, *g0xT, *outs, *spred, *cbA, *cbB;
    cudaGetSymbolAddress((void**)&pre1, g_pre1);
    cudaGetSymbolAddress((void**)&pre2, g_pre2);
    cudaGetSymbolAddress((void**)&g0xT, g_g0xT);
    cudaGetSymbolAddress((void**)&outs, g_outs);
    cudaGetSymbolAddress((void**)&spred, g_spred);
    cudaGetSymbolAddress((void**)&cbA, g_cbA);
    cudaGetSymbolAddress((void**)&cbB, g_cbB);

    init_kernel<<<64, 256>>>();

    // pre-net
    gemm_kernel<<<dim3(4, 600), 256>>>(S_pad, pre_W1, pre_b1, nullptr, pre1,
                                       MROWS, DPRE, DSPEC, DSPEC, 1, 1, 0);
    gemm_kernel<<<dim3(4, 600), 256>>>(pre1, pre_W2, pre_b2, nullptr, pre2,
                                       MROWS, DPRE, DPRE, DPRE, 0, 1, 0);
    // layer-0 input gates (ctx zero -> first 256 cols of Wih0), + both biases,
    // stored transposed [t][gate][b]
    gemm_kernel<<<dim3(64, 600), 256>>>(pre2, Wih0, bih0, bhh0, g0xT,
                                        MROWS, G4, DPRE, DPRE + 128, 0, 0, 2);
    // full recurrence in one persistent kernel
    lstm_persistent<<<NBLK, 256>>>(Whh0, Wih1, Whh1, bih1, bhh1);

    // output linear (ctx zero -> first 1024 cols of lin_W), write [B][552][600]
    gemm_kernel<<<dim3(9, 600), 256>>>(outs, lin_W, lin_b, nullptr, spred,
                                       MROWS, DSPEC, DH, DH + 128, 0, 0, 1);
    // postnet
    conv_kernel<<<dim3(3, 32, 64), 128>>>(spred, cw1, cb1, cbA, DSPEC, 512, 0, nullptr);
    conv_kernel<<<dim3(3, 32, 64), 128>>>(cbA, cw2, cb2, cbB, 512, 512, 0, nullptr);
    conv_kernel<<<dim3(3, 32, 64), 128>>>(cbB, cw3, cb3, cbA, 512, 512, 0, nullptr);
    conv_kernel<<<dim3(3, 32, 64), 128>>>(cbA, cw4, cb4, cbB, 512, 512, 0, nullptr);
    conv_kernel<<<dim3(3, 35, 64), 128>>>(cbB, cw5, cb5, (float*)d_out, 512, DSPEC, 1, spred);
    (void)in_sizes; (void)n_in; (void)out_size;
}

// round 3
// speedup vs baseline: 1.6299x; 1.6299x over previous
#include <cuda_runtime.h>
#include <math.h>
#include <stdint.h>

#define L_SEQ   600
#define BATCH   64
#define DSPEC   552
#define DPRE    256
#define DH      1024
#define G4      4096
#define MROWS   (L_SEQ*BATCH)   // 38400
#define NBLK    64

// ---------------- static device scratch ----------------
static __device__ float g_pre1 [(size_t)MROWS*DPRE];
static __device__ float g_pre2 [(size_t)MROWS*DPRE];
static __device__ float g_g0xT [(size_t)L_SEQ*G4*BATCH];     // [t][gate_row][b]
static __device__ float g_wp0  [(size_t)64*32*2048];         // packed Whh0 (tf32)
static __device__ float g_wp1  [(size_t)64*64*2048];         // packed [Wih1|Whh1] (tf32)
static __device__ float g_ht0  [2][DH*BATCH];                // transposed h0 [k][b], tf32-rounded
static __device__ float g_ht1  [2][DH*BATCH];
static __device__ float g_c0t  [DH*BATCH];
static __device__ float g_c1t  [DH*BATCH];
static __device__ float g_outs [(size_t)MROWS*DH];           // [t][b][1024] full fp32
static __device__ float g_spred[(size_t)BATCH*DSPEC*L_SEQ];  // [B][552][600]
static __device__ float g_cbA  [(size_t)BATCH*DSPEC*L_SEQ];
static __device__ float g_cbB  [(size_t)BATCH*DSPEC*L_SEQ];
static __device__ unsigned int g_barctr;

__device__ __forceinline__ float sigmoidf_(float x) { return 1.0f / (1.0f + expf(-x)); }

__device__ __forceinline__ float tf32r(float x) {
    unsigned u; asm("cvt.rna.tf32.f32 %0, %1;" : "=r"(u) : "f"(x));
    return __uint_as_float(u);
}

__device__ __forceinline__ void cpasync16(void* dst_smem, const void* src) {
    unsigned s = (unsigned)__cvta_generic_to_shared(dst_smem);
    asm volatile("cp.async.cg.shared.global [%0], [%1], 16;" :: "r"(s), "l"(src));
}
__device__ __forceinline__ void cp_commit() {
    asm volatile("cp.async.commit_group;" ::: "memory");
}
__device__ __forceinline__ void cp_wait1() {
    asm volatile("cp.async.wait_group 1;" ::: "memory");
}

__device__ __forceinline__ void mma_tf32(float& d0, float& d1, float& d2, float& d3,
                                         uint4 a, unsigned b0, unsigned b1) {
    asm volatile(
        "mma.sync.aligned.m16n8k8.row.col.f32.tf32.tf32.f32 "
        "{%0,%1,%2,%3}, {%4,%5,%6,%7}, {%8,%9}, {%0,%1,%2,%3};"
        : "+f"(d0), "+f"(d1), "+f"(d2), "+f"(d3)
        : "r"(a.x), "r"(a.y), "r"(a.z), "r"(a.w), "r"(b0), "r"(b1));
}

// ---------------- init ----------------
__global__ void init_kernel() {
    int i = blockIdx.x * blockDim.x + threadIdx.x;
    if (i == 0) g_barctr = 0u;
    int stride = gridDim.x * blockDim.x;
    for (int j = i; j < DH*BATCH; j += stride) {
        g_ht0[0][j] = 0.f; g_ht1[0][j] = 0.f; g_c0t[j] = 0.f; g_c1t[j] = 0.f;
    }
}

// ---------------- weight pack kernels (fragment-order, tf32-rounded) ----------------
// packed element i = ((((blk*NCH + chunk)*4 + mh)*4 + kc)*32 + lane)*4 + reg
// a_reg layout: reg j -> row16 = (lane>>2) + (j&1)*8 ; col8 = (lane&3) + ((j>>1)&1)*4
// gate row j_g = mh*1024 + blk*16 + row16 ; k = chunk*32 + kc*8 + col8
__global__ void pack_w0(const float* __restrict__ Whh0, float* __restrict__ wp) {
    size_t i = (size_t)blockIdx.x * blockDim.x + threadIdx.x;
    if (i >= (size_t)64*32*2048) return;
    int reg = i & 3, lane = (i >> 2) & 31, kc = (i >> 7) & 3, mh = (i >> 9) & 3;
    int chunk = (i >> 11) & 31, blk = (int)(i >> 16);
    int row16 = (lane >> 2) + (reg & 1) * 8;
    int col8  = (lane & 3) + ((reg >> 1) & 1) * 4;
    int j = mh * 1024 + blk * 16 + row16;
    int k = chunk * 32 + kc * 8 + col8;
    wp[i] = tf32r(Whh0[(size_t)j * 1024 + k]);
}
__global__ void pack_w1(const float* __restrict__ Wih1, const float* __restrict__ Whh1,
                        float* __restrict__ wp) {
    size_t i = (size_t)blockIdx.x * blockDim.x + threadIdx.x;
    if (i >= (size_t)64*64*2048) return;
    int reg = i & 3, lane = (i >> 2) & 31, kc = (i >> 7) & 3, mh = (i >> 9) & 3;
    int chunk = (i >> 11) & 63, blk = (int)(i >> 17);
    int row16 = (lane >> 2) + (reg & 1) * 8;
    int col8  = (lane & 3) + ((reg >> 1) & 1) * 4;
    int j = mh * 1024 + blk * 16 + row16;
    int k = chunk * 32 + kc * 8 + col8;
    float v = (k < 1024) ? Wih1[(size_t)j * 1024 + k] : Whh1[(size_t)j * 1024 + (k - 1024)];
    wp[i] = tf32r(v);
}

// ---------------- generic GEMM (unchanged from R2) ----------------
__global__ void gemm_kernel(const float* __restrict__ A, const float* __restrict__ W,
                            const float* __restrict__ b1, const float* __restrict__ b2,
                            float* __restrict__ C, int M, int N, int K, int wstride,
                            int a_shift, int act, int c_mode)
{
    __shared__ float sA[16][64];
    __shared__ float sW[16][64];
    int tid = threadIdx.x;
    int m0 = blockIdx.y * 64, n0 = blockIdx.x * 64;
    int tm = tid & 15, tn = tid >> 4;
    float acc[4][4];
#pragma unroll
    for (int i = 0; i < 4; i++)
#pragma unroll
        for (int j = 0; j < 4; j++) acc[i][j] = 0.f;

    for (int k0 = 0; k0 < K; k0 += 16) {
        {
            int m = tid >> 2, kq = tid & 3;
            int gm = m0 + m, gk = k0 + kq * 4;
            float4 v = make_float4(0.f, 0.f, 0.f, 0.f);
            int row = gm; bool okrow = true;
            if (a_shift) { row = gm - 64; okrow = (row >= 0); }
            if (okrow) {
                const float* p = A + (size_t)row * K + gk;
                if (gk + 4 <= K) v = *(const float4*)p;
                else {
                    if (gk + 0 < K) v.x = p[0];
                    if (gk + 1 < K) v.y = p[1];
                    if (gk + 2 < K) v.z = p[2];
                    if (gk + 3 < K) v.w = p[3];
                }
            }
            sA[kq*4+0][m] = v.x; sA[kq*4+1][m] = v.y; sA[kq*4+2][m] = v.z; sA[kq*4+3][m] = v.w;
        }
        {
            int n = tid >> 2, kq = tid & 3;
            int gn = n0 + n, gk = k0 + kq * 4;
            float4 v = make_float4(0.f, 0.f, 0.f, 0.f);
            if (gn < N) {
                const float* p = W + (size_t)gn * wstride + gk;
                if (gk + 4 <= K) v = *(const float4*)p;
                else {
                    if (gk + 0 < K) v.x = p[0];
                    if (gk + 1 < K) v.y = p[1];
                    if (gk + 2 < K) v.z = p[2];
                    if (gk + 3 < K) v.w = p[3];
                }
            }
            sW[kq*4+0][n] = v.x; sW[kq*4+1][n] = v.y; sW[kq*4+2][n] = v.z; sW[kq*4+3][n] = v.w;
        }
        __syncthreads();
#pragma unroll
        for (int k = 0; k < 16; k++) {
            float4 av = *(float4*)&sA[k][tm*4];
            float4 wv = *(float4*)&sW[k][tn*4];
            float a[4] = {av.x, av.y, av.z, av.w};
            float w[4] = {wv.x, wv.y, wv.z, wv.w};
#pragma unroll
            for (int i = 0; i < 4; i++)
#pragma unroll
                for (int j = 0; j < 4; j++) acc[i][j] += a[i] * w[j];
        }
        __syncthreads();
    }
#pragma unroll
    for (int i = 0; i < 4; i++) {
        int gm = m0 + tm*4 + i;
#pragma unroll
        for (int j = 0; j < 4; j++) {
            int gn = n0 + tn*4 + j;
            if (gn < N) {
                float v = acc[i][j];
                if (b1) v += b1[gn];
                if (b2) v += b2[gn];
                if (act) v = fmaxf(v, 0.f);
                if (c_mode == 0) C[(size_t)gm * N + gn] = v;
                else if (c_mode == 1) {
                    int t = gm >> 6, b = gm & 63;
                    C[(size_t)b * N * 600 + (size_t)gn * 600 + t] = v;
                } else {
                    int t = gm >> 6, b = gm & 63;
                    C[((size_t)t * N + gn) * 64 + b] = v;
                }
            }
        }
    }
}

// ---------------- persistent LSTM recurrence (tf32 mma.sync) ----------------
// 64 blocks x 256 threads. Block owns 64 gate rows: m=0..63 -> j = (m>>4)*1024 + jj0 + (m&15),
// jj0 = blockIdx*16. Warp wid: mg=wid&3 (16-row gate quarter), ng=wid>>2 (32-col batch half).
// K chunks of 32 (4 sub-chunks of k8). 3-stage cp.async ring.
// Stage layout (floats): [0,2048) = A frags [mh][kc][lane][reg]; [2048,4096) = h tile
// [k][64] with col swizzle n^( (k&3)*8 ). gsum at offset 12288: [64][66].

__device__ __forceinline__ void grid_bar(unsigned int target) {
    __threadfence();
    __syncthreads();
    if (threadIdx.x == 0) {
        atomicAdd(&g_barctr, 1u);
        unsigned int cur;
        do {
            asm volatile("ld.acquire.gpu.u32 %0, [%1];" : "=r"(cur) : "l"(&g_barctr) : "memory");
        } while (cur < target);
    }
    __syncthreads();
}

__device__ __forceinline__ void fill_chunk(float* stage, const float* __restrict__ wsrc,
                                           const float* __restrict__ hsrc, int tid) {
    cpasync16(stage + tid * 8,     wsrc + tid * 8);
    cpasync16(stage + tid * 8 + 4, wsrc + tid * 8 + 4);
#pragma unroll
    for (int q = 0; q < 2; q++) {
        int v = tid * 2 + q;
        int k = v >> 4, n4 = (v & 15) * 4;
        int sc = n4 ^ ((k & 3) * 8);
        cpasync16(stage + 2048 + k * 64 + sc, hsrc + k * 64 + n4);
    }
}

template<int NC>
__device__ __forceinline__ void mma_phase(float* smem, float* gsum,
                                          const float* __restrict__ wp,
                                          const float* __restrict__ hA,
                                          const float* __restrict__ hB,
                                          int tid, int lane, int mg, int ng)
{
    float d[4][4];
#pragma unroll
    for (int f = 0; f < 4; f++)
#pragma unroll
        for (int r = 0; r < 4; r++) d[f][r] = 0.f;

    int colsw[4];
#pragma unroll
    for (int f = 0; f < 4; f++)
        colsw[f] = (((ng * 4 + f) * 8) + (lane >> 2)) ^ ((lane & 3) * 8);

    // prologue: chunks 0,1
    fill_chunk(smem + 0 * 4096, wp + 0 * 2048, hA + 0 * 2048, tid);
    cp_commit();
    {
        const float* h1 = (1 < 32 || NC == 32) ? hA + 1 * 2048 : hB;  // chunk1 always < 32
        fill_chunk(smem + 1 * 4096, wp + 1 * 2048, h1, tid);
        cp_commit();
    }

    for (int c = 0; c < NC; c++) {
        cp_wait1();
        __syncthreads();
        int cn = c + 2;
        if (cn < NC) {
            const float* hs = (cn < 32) ? hA + cn * 2048 : hB + (cn - 32) * 2048;
            fill_chunk(smem + (cn % 3) * 4096, wp + (size_t)cn * 2048, hs, tid);
        }
        cp_commit();

        const float* sA = smem + (c % 3) * 4096;
        const unsigned* sHu = (const unsigned*)(sA + 2048);
#pragma unroll
        for (int kc = 0; kc < 4; kc++) {
            uint4 a = *(const uint4*)(sA + ((mg * 4 + kc) * 32 + lane) * 4);
            int kb = (kc * 8 + (lane & 3)) * 64;
#pragma unroll
            for (int f = 0; f < 4; f++) {
                unsigned b0 = sHu[kb + colsw[f]];
                unsigned b1 = sHu[kb + 256 + colsw[f]];
                mma_tf32(d[f][0], d[f][1], d[f][2], d[f][3], a, b0, b1);
            }
        }
    }

    // store D fragments to gsum [64][66]
    int r0 = mg * 16 + (lane >> 2);
#pragma unroll
    for (int f = 0; f < 4; f++) {
        int cb = (ng * 4 + f) * 8 + (lane & 3) * 2;
        *(float2*)&gsum[r0 * 66 + cb]       = make_float2(d[f][0], d[f][1]);
        *(float2*)&gsum[(r0 + 8) * 66 + cb] = make_float2(d[f][2], d[f][3]);
    }
    __syncthreads();
}

__global__ __launch_bounds__(256, 1)
void lstm_persistent(const float* __restrict__ wp0, const float* __restrict__ wp1,
                     const float* __restrict__ bih1, const float* __restrict__ bhh1)
{
    extern __shared__ float smem[];
    float* gsum = smem + 12288;

    int tid = threadIdx.x;
    int lane = tid & 31, wid = tid >> 5;
    int mg = wid & 3, ng = wid >> 2;
    int jj0 = blockIdx.x * 16;
    const float* wpb0 = wp0 + (size_t)blockIdx.x * 32 * 2048;
    const float* wpb1 = wp1 + (size_t)blockIdx.x * 64 * 2048;
    unsigned int ep = 0;

    for (int t = 0; t < L_SEQ; t++) {
        // ---------- phase A : layer 0 ----------
        const float* hin = g_ht0[t & 1];
        float*       h0w = g_ht0[(t + 1) & 1];
        mma_phase<32>(smem, gsum, wpb0, hin, hin, tid, lane, mg, ng);
        {
            const float* gx = g_g0xT + (size_t)t * G4 * 64;
#pragma unroll
            for (int e = 0; e < 4; e++) {
                int idx = e * 256 + tid;
                int b = idx & 63, jr = idx >> 6;
                int jj = jj0 + jr;
                float gi = gsum[jr * 66 + b]        + gx[(size_t)(       jj) * 64 + b];
                float gf = gsum[(16 + jr) * 66 + b] + gx[(size_t)(1024 + jj) * 64 + b];
                float gg = gsum[(32 + jr) * 66 + b] + gx[(size_t)(2048 + jj) * 64 + b];
                float go = gsum[(48 + jr) * 66 + b] + gx[(size_t)(3072 + jj) * 64 + b];
                float cc = g_c0t[jj * 64 + b];
                float cn = sigmoidf_(gf) * cc + sigmoidf_(gi) * tanhf(gg);
                float hn = sigmoidf_(go) * tanhf(cn);
                g_c0t[jj * 64 + b] = cn;
                h0w[jj * 64 + b] = tf32r(hn);
            }
        }
        grid_bar(++ep * NBLK);

        // ---------- phase B : layer 1 ----------
        const float* h0n  = g_ht0[(t + 1) & 1];
        const float* h1in = g_ht1[t & 1];
        float*       h1w  = g_ht1[(t + 1) & 1];
        mma_phase<64>(smem, gsum, wpb1, h0n, h1in, tid, lane, mg, ng);
        {
#pragma unroll
            for (int e = 0; e < 4; e++) {
                int idx = e * 256 + tid;
                int b = idx & 63, jr = idx >> 6;
                int jj = jj0 + jr;
                float gi = gsum[jr * 66 + b]        + bih1[       jj] + bhh1[       jj];
                float gf = gsum[(16 + jr) * 66 + b] + bih1[1024 + jj] + bhh1[1024 + jj];
                float gg = gsum[(32 + jr) * 66 + b] + bih1[2048 + jj] + bhh1[2048 + jj];
                float go = gsum[(48 + jr) * 66 + b] + bih1[3072 + jj] + bhh1[3072 + jj];
                float cc = g_c1t[jj * 64 + b];
                float cn = sigmoidf_(gf) * cc + sigmoidf_(gi) * tanhf(gg);
                float hn = sigmoidf_(go) * tanhf(cn);
                g_c1t[jj * 64 + b] = cn;
                h1w[jj * 64 + b] = tf32r(hn);
                g_outs[((size_t)t * 64 + b) * DH + jj] = hn;
            }
        }
        grid_bar(++ep * NBLK);
    }
}

// ---------------- conv1d (K=5, same padding) (unchanged from R2) ----------------
__global__ void conv_kernel(const float* __restrict__ x, const float* __restrict__ w,
                            const float* __restrict__ bias, float* __restrict__ out,
                            int Cin, int Cout, int mode, const float* __restrict__ spred)
{
    __shared__ float sx[8][260];
    __shared__ float swt[16][8][5];
    int b   = blockIdx.z;
    int co0 = blockIdx.y * 16;
    int lt0 = blockIdx.x * 256;
    int tid = threadIdx.x;
    int tc = tid >> 5;
    int tl = tid & 31;
    float acc[4][8];
#pragma unroll
    for (int ci = 0; ci < 4; ci++)
#pragma unroll
        for (int j = 0; j < 8; j++) acc[ci][j] = 0.f;

    for (int ci0 = 0; ci0 < Cin; ci0 += 8) {
        __syncthreads();
        for (int idx = tid; idx < 8 * 260; idx += 128) {
            int ci = idx / 260, lc = idx % 260;
            int gl = lt0 - 2 + lc;
            sx[ci][lc] = (gl >= 0 && gl < 600) ? x[((size_t)b * Cin + ci0 + ci) * 600 + gl] : 0.f;
        }
        for (int idx = tid; idx < 16 * 8 * 5; idx += 128) {
            int co = idx / 40, r = idx % 40;
            int ci = r / 5, k = r % 5;
            float v = 0.f;
            if (co0 + co < Cout) v = w[(((size_t)(co0 + co)) * Cin + ci0 + ci) * 5 + k];
            swt[co][ci][k] = v;
        }
        __syncthreads();
#pragma unroll
        for (int ci = 0; ci < 8; ci++) {
            float xr[12];
#pragma unroll
            for (int i = 0; i < 12; i++) xr[i] = sx[ci][tl * 8 + i];
#pragma unroll
            for (int k = 0; k < 5; k++)
#pragma unroll
                for (int cg = 0; cg < 4; cg++) {
                    float wv = swt[tc * 4 + cg][ci][k];
#pragma unroll
                    for (int j = 0; j < 8; j++) acc[cg][j] += wv * xr[j + k];
                }
        }
    }
#pragma unroll
    for (int cg = 0; cg < 4; cg++) {
        int co = co0 + tc * 4 + cg;
        if (co >= Cout) continue;
#pragma unroll
        for (int j = 0; j < 8; j++) {
            int l = lt0 + tl * 8 + j;
            if (l >= 600) continue;
            float v = acc[cg][j] + bias[co];
            if (mode == 0)
                out[((size_t)b * Cout + co) * 600 + l] = tanhf(v);
            else {
                v += spred[((size_t)b * Cout + co) * 600 + l];
                out[((size_t)l * 64 + b) * 552 + co] = v;
            }
        }
    }
}

// ---------------- launcher ----------------
extern "C" void kernel_launch(void* const* d_in, const int* in_sizes, int n_in,
                              void* d_out, int out_size)
{
    const float* S_pad  = (const float*)d_in[0];
    const float* pre_W1 = (const float*)d_in[1];
    const float* pre_b1 = (const float*)d_in[2];
    const float* pre_W2 = (const float*)d_in[3];
    const float* pre_b2 = (const float*)d_in[4];
    const float* Wih0   = (const float*)d_in[5];
    const float* Whh0   = (const float*)d_in[6];
    const float* bih0   = (const float*)d_in[7];
    const float* bhh0   = (const float*)d_in[8];
    const float* Wih1   = (const float*)d_in[9];
    const float* Whh1   = (const float*)d_in[10];
    const float* bih1   = (const float*)d_in[11];
    const float* bhh1   = (const float*)d_in[12];
    const float* lin_W  = (const float*)d_in[13];
    const float* lin_b  = (const float*)d_in[14];
    const float* cw1 = (const float*)d_in[15];
    const float* cb1 = (const float*)d_in[16];
    const float* cw2 = (const float*)d_in[17];
    const float* cb2 = (const float*)d_in[18];
    const float* cw3 = (const float*)d_in[19];
    const float* cb3 = (const float*)d_in[20];
    const float* cw4 = (const float*)d_in[21];
    const float* cb4 = (const float*)d_in[22];
    const float* cw5 = (const float*)d_in[23];
    const float* cb5 = (const float*)d_in[24];

    float *pre1, *pre2, *g0xT, *wp0, *wp1, *outs, *spred, *cbA, *cbB;
    cudaGetSymbolAddress((void**)&pre1, g_pre1);
    cudaGetSymbolAddress((void**)&pre2, g_pre2);
    cudaGetSymbolAddress((void**)&g0xT, g_g0xT);
    cudaGetSymbolAddress((void**)&wp0, g_wp0);
    cudaGetSymbolAddress((void**)&wp1, g_wp1);
    cudaGetSymbolAddress((void**)&outs, g_outs);
    cudaGetSymbolAddress((void**)&spred, g_spred);
    cudaGetSymbolAddress((void**)&cbA, g_cbA);
    cudaGetSymbolAddress((void**)&cbB, g_cbB);

    const int lstm_smem = (12288 + 64 * 66) * 4;  // 66048 bytes
    cudaFuncSetAttribute(lstm_persistent, cudaFuncAttributeMaxDynamicSharedMemorySize, lstm_smem);

    init_kernel<<<64, 256>>>();
    pack_w0<<<4096, 1024>>>(Whh0, wp0);
    pack_w1<<<8192, 1024>>>(Wih1, Whh1, wp1);

    // pre-net
    gemm_kernel<<<dim3(4, 600), 256>>>(S_pad, pre_W1, pre_b1, nullptr, pre1,
                                       MROWS, DPRE, DSPEC, DSPEC, 1, 1, 0);
    gemm_kernel<<<dim3(4, 600), 256>>>(pre1, pre_W2, pre_b2, nullptr, pre2,
                                       MROWS, DPRE, DPRE, DPRE, 0, 1, 0);
    // layer-0 input gates (ctx zero -> first 256 cols of Wih0), + both biases,
    // stored transposed [t][gate_row][b]
    gemm_kernel<<<dim3(64, 600), 256>>>(pre2, Wih0, bih0, bhh0, g0xT,
                                        MROWS, G4, DPRE, DPRE + 128, 0, 0, 2);
    // full recurrence (tf32 tensor cores)
    lstm_persistent<<<NBLK, 256, lstm_smem>>>(wp0, wp1, bih1, bhh1);

    // output linear (ctx zero -> first 1024 cols of lin_W), write [B][552][600]
    gemm_kernel<<<dim3(9, 600), 256>>>(outs, lin_W, lin_b, nullptr, spred,
                                       MROWS, DSPEC, DH, DH + 128, 0, 0, 1);
    // postnet
    conv_kernel<<<dim3(3, 32, 64), 128>>>(spred, cw1, cb1, cbA, DSPEC, 512, 0, nullptr);
    conv_kernel<<<dim3(3, 32, 64), 128>>>(cbA, cw2, cb2, cbB, 512, 512, 0, nullptr);
    conv_kernel<<<dim3(3, 32, 64), 128>>>(cbB, cw3, cb3, cbA, 512, 512, 0, nullptr);
    conv_kernel<<<dim3(3, 32, 64), 128>>>(cbA, cw4, cb4, cbB, 512, 512, 0, nullptr);
    conv_kernel<<<dim3(3, 35, 64), 128>>>(cbB, cw5, cb5, (float*)d_out, 512, DSPEC, 1, spred);
    (void)in_sizes; (void)n_in; (void)out_size;
}